// round 12
// baseline (speedup 1.0000x reference)
#include <cuda_runtime.h>
#include <cuda_bf16.h>
#include <math.h>

// Problem constants
#define BGRAPH 128
#define NNODE  512
#define NN     (BGRAPH*NNODE)      // 65536
#define DFEAT  128
#define EDGES  524288
#define KEEP1  410
#define KEEP2  328
#define BUCKET_CAP 32

// ---------------- scratch (device globals; no runtime allocation) ----------------
__device__ float g_agg[NN*DFEAT];   // aggregated neighbor features
__device__ float g_h  [NN*DFEAT];   // conv1 output (gated in place by pool1)
__device__ float g_h2 [NN*DFEAT];   // conv2 output
__device__ float g_score[NN];       // node scores (written by GEMM epilogue)
__device__ int   g_deg[NN];
__device__ int   g_bucket[NN*BUCKET_CAP];
__device__ int   g_ovf_cnt;
__device__ int   g_ovf_d[EDGES];
__device__ int   g_ovf_s[EDGES];
__device__ unsigned char g_m1[NN];
__device__ float g_x1[BGRAPH*256];
__device__ float g_x2[BGRAPH*256];

// ---------------- packed fp32x2 helpers (Blackwell) ----------------
__device__ __forceinline__ unsigned long long pk2(float x) {
    unsigned long long d;
    asm("mov.b64 %0, {%1, %1};" : "=l"(d) : "f"(x));
    return d;
}
__device__ __forceinline__ unsigned long long ffma2(unsigned long long a,
                                                    unsigned long long b,
                                                    unsigned long long c) {
    unsigned long long d;
    asm("fma.rn.f32x2 %0, %1, %2, %3;" : "=l"(d) : "l"(a), "l"(b), "l"(c));
    return d;
}
__device__ __forceinline__ void unpk2(unsigned long long v, float& lo, float& hi) {
    asm("mov.b64 {%0, %1}, %2;" : "=f"(lo), "=f"(hi) : "l"(v));
}

// ---------------- bucketed edge build ----------------
__global__ void zero_kernel() {
    int i = blockIdx.x * blockDim.x + threadIdx.x;
    if (i < NN) g_deg[i] = 0;
    if (i == 0) g_ovf_cnt = 0;
}

__global__ void bucket_scatter_kernel(const int* __restrict__ src,
                                      const int* __restrict__ dst) {
    int i = blockIdx.x * blockDim.x + threadIdx.x;
    if (i < EDGES) {
        int d = dst[i];
        int s = src[i];
        int pos = atomicAdd(&g_deg[d], 1);
        if (pos < BUCKET_CAP) {
            g_bucket[d * BUCKET_CAP + pos] = s;
        } else {
            int o = atomicAdd(&g_ovf_cnt, 1);
            g_ovf_d[o] = d;
            g_ovf_s[o] = s;
        }
    }
}

// ---------------- neighbor aggregation: warp/node, bucket idx, MLP=8 ----------------
template<int LAYER>
__global__ void __launch_bounds__(256)
agg_gather_kernel(const float* __restrict__ xin) {
    const float* feat = (LAYER == 1) ? xin : g_h;
    int gw = (blockIdx.x * blockDim.x + threadIdx.x) >> 5;
    int lane = threadIdx.x & 31;
    if (gw >= NN) return;

    int nv = __ldg(&g_deg[gw]);
    int m = min(nv, BUCKET_CAP);
    int idx = 0;
    if (lane < m) idx = __ldg(&g_bucket[gw * BUCKET_CAP + lane]);

    const float4* f4 = (const float4*)feat;
    float a0 = 0.f, a1 = 0.f, a2 = 0.f, a3 = 0.f;
    int e = 0;
    for (; e + 8 <= m; e += 8) {
        int i0 = __shfl_sync(0xffffffffu, idx, e);
        int i1 = __shfl_sync(0xffffffffu, idx, e + 1);
        int i2 = __shfl_sync(0xffffffffu, idx, e + 2);
        int i3 = __shfl_sync(0xffffffffu, idx, e + 3);
        int i4 = __shfl_sync(0xffffffffu, idx, e + 4);
        int i5 = __shfl_sync(0xffffffffu, idx, e + 5);
        int i6 = __shfl_sync(0xffffffffu, idx, e + 6);
        int i7 = __shfl_sync(0xffffffffu, idx, e + 7);
        float4 v0 = __ldg(f4 + (size_t)i0 * 32 + lane);
        float4 v1 = __ldg(f4 + (size_t)i1 * 32 + lane);
        float4 v2 = __ldg(f4 + (size_t)i2 * 32 + lane);
        float4 v3 = __ldg(f4 + (size_t)i3 * 32 + lane);
        float4 v4 = __ldg(f4 + (size_t)i4 * 32 + lane);
        float4 v5 = __ldg(f4 + (size_t)i5 * 32 + lane);
        float4 v6 = __ldg(f4 + (size_t)i6 * 32 + lane);
        float4 v7 = __ldg(f4 + (size_t)i7 * 32 + lane);
        a0 += ((v0.x + v1.x) + (v2.x + v3.x)) + ((v4.x + v5.x) + (v6.x + v7.x));
        a1 += ((v0.y + v1.y) + (v2.y + v3.y)) + ((v4.y + v5.y) + (v6.y + v7.y));
        a2 += ((v0.z + v1.z) + (v2.z + v3.z)) + ((v4.z + v5.z) + (v6.z + v7.z));
        a3 += ((v0.w + v1.w) + (v2.w + v3.w)) + ((v4.w + v5.w) + (v6.w + v7.w));
    }
    for (; e + 4 <= m; e += 4) {
        int i0 = __shfl_sync(0xffffffffu, idx, e);
        int i1 = __shfl_sync(0xffffffffu, idx, e + 1);
        int i2 = __shfl_sync(0xffffffffu, idx, e + 2);
        int i3 = __shfl_sync(0xffffffffu, idx, e + 3);
        float4 v0 = __ldg(f4 + (size_t)i0 * 32 + lane);
        float4 v1 = __ldg(f4 + (size_t)i1 * 32 + lane);
        float4 v2 = __ldg(f4 + (size_t)i2 * 32 + lane);
        float4 v3 = __ldg(f4 + (size_t)i3 * 32 + lane);
        a0 += (v0.x + v1.x) + (v2.x + v3.x);
        a1 += (v0.y + v1.y) + (v2.y + v3.y);
        a2 += (v0.z + v1.z) + (v2.z + v3.z);
        a3 += (v0.w + v1.w) + (v2.w + v3.w);
    }
    for (; e < m; ++e) {
        int i0 = __shfl_sync(0xffffffffu, idx, e);
        float4 v0 = __ldg(f4 + (size_t)i0 * 32 + lane);
        a0 += v0.x; a1 += v0.y; a2 += v0.z; a3 += v0.w;
    }
    if (nv > BUCKET_CAP) {   // correctness fallback; ~never taken
        int oc = g_ovf_cnt;
        for (int t = 0; t < oc; ++t) {
            if (g_ovf_d[t] == gw) {
                float4 v0 = __ldg(f4 + (size_t)g_ovf_s[t] * 32 + lane);
                a0 += v0.x; a1 += v0.y; a2 += v0.z; a3 += v0.w;
            }
        }
    }
    ((float4*)g_agg)[(size_t)gw * 32 + lane] = make_float4(a0, a1, a2, a3);
}

// ---------------- conv GEMM: out = relu(A1@Wr + A2@Wn + b); score epilogue ----
// Tile 128x128, K=256, 256 threads, f32x2 packed FMA.
// 16-wide K chunks (16 barriers total), static double buffer, LDS.128 A reads.
// 16 chunks: chunk C<8 -> (A1, Wr) k0=16C ; C>=8 -> (A2, Wn) k0=16(C-8).

#define CONV_PREFETCH_A(NC)                                                   \
    {                                                                         \
        const float* A_ = ((NC) < 8) ? A1 : A2;                               \
        int k0_ = ((NC) & 7) * 16;                                            \
        av0 = *(const float4*)&A_[(size_t)(row0 + lrow) * 128 + k0_ + lk4];   \
        av1 = *(const float4*)&A_[(size_t)(row0 + lrow) * 128 + k0_ + 8 + lk4];\
    }

#define CONV_PREFETCH_W(NC)                                                   \
    {                                                                         \
        const float* W_ = ((NC) < 8) ? Wr : Wn;                               \
        int k0_ = ((NC) & 7) * 16;                                            \
        wv0 = *(const float4*)&W_[(size_t)(k0_ + ry) * 128 + cx * 4];         \
        wv1 = *(const float4*)&W_[(size_t)(k0_ + 8 + ry) * 128 + cx * 4];     \
    }

#define CONV_STS(ASB, WSB)                                                    \
    {                                                                         \
        ASB[lk4 + 0][lrow] = av0.x;                                           \
        ASB[lk4 + 1][lrow] = av0.y;                                           \
        ASB[lk4 + 2][lrow] = av0.z;                                           \
        ASB[lk4 + 3][lrow] = av0.w;                                           \
        ASB[lk4 + 8][lrow] = av1.x;                                           \
        ASB[lk4 + 9][lrow] = av1.y;                                           \
        ASB[lk4 + 10][lrow] = av1.z;                                          \
        ASB[lk4 + 11][lrow] = av1.w;                                          \
        *(float4*)&WSB[ry][cx * 4] = wv0;                                     \
        *(float4*)&WSB[ry + 8][cx * 4] = wv1;                                 \
    }

#define CONV_COMPUTE_HALF(ASB, WSB, KOFF)                                     \
    _Pragma("unroll")                                                         \
    for (int k = (KOFF); k < (KOFF) + 8; ++k) {                               \
        unsigned long long ap[8];                                             \
        _Pragma("unroll")                                                     \
        for (int q = 0; q < 4; ++q) {                                         \
            ulonglong2 a2v = *(const ulonglong2*)&ASB[k][ry * 16 + 4 * q];    \
            ap[2 * q]     = a2v.x;                                            \
            ap[2 * q + 1] = a2v.y;                                            \
        }                                                                     \
        _Pragma("unroll")                                                     \
        for (int j = 0; j < 4; ++j) {                                         \
            unsigned long long wp = pk2(WSB[k][cx + 32 * j]);                 \
            _Pragma("unroll")                                                 \
            for (int r = 0; r < 8; ++r)                                       \
                acc[r][j] = ffma2(ap[r], wp, acc[r][j]);                      \
        }                                                                     \
    }

template<int LAYER>
__global__ void __launch_bounds__(256, 2)
conv_gemm_kernel(const float* __restrict__ A1in,
                 const float* __restrict__ Wr,
                 const float* __restrict__ Wn,
                 const float* __restrict__ bias,
                 const float* __restrict__ p) {
    const float* A1 = (LAYER == 1) ? A1in : g_h;
    const float* A2 = g_agg;
    float* Out = (LAYER == 1) ? g_h : g_h2;

    __shared__ float As0[16][128];
    __shared__ float Ws0[16][128];
    __shared__ float As1[16][128];
    __shared__ float Ws1[16][128];

    int tid = threadIdx.x;
    int cx = tid & 31;        // column group: cols cx + 32*j
    int ry = tid >> 5;        // row group: rows ry*16 .. ry*16+15 (8 pairs)
    int row0 = blockIdx.x * 128;
    int lrow = tid >> 1;              // A loader row 0..127
    int lk4 = (tid & 1) * 4;          // A loader k sub-offset

    unsigned long long acc[8][4];
#pragma unroll
    for (int r = 0; r < 8; ++r)
#pragma unroll
        for (int j = 0; j < 4; ++j) acc[r][j] = 0ull;

    float4 av0, av1, wv0, wv1;

    // preload chunk 0 into buffer 0
    CONV_PREFETCH_A(0);
    CONV_PREFETCH_W(0);
    CONV_STS(As0, Ws0);
    __syncthreads();

#pragma unroll 1
    for (int c2 = 0; c2 < 8; ++c2) {
        int c0 = 2 * c2;

        // chunk c0 in buf0: prefetch c0+1 (A early, W mid), compute, stage buf1
        CONV_PREFETCH_A(c0 + 1);
        CONV_COMPUTE_HALF(As0, Ws0, 0);
        CONV_PREFETCH_W(c0 + 1);
        CONV_COMPUTE_HALF(As0, Ws0, 8);
        CONV_STS(As1, Ws1);
        __syncthreads();

        // chunk c0+1 in buf1: prefetch c0+2 (except last), compute, stage buf0
        if (c2 < 7) { CONV_PREFETCH_A(c0 + 2); }
        CONV_COMPUTE_HALF(As1, Ws1, 0);
        if (c2 < 7) { CONV_PREFETCH_W(c0 + 2); }
        CONV_COMPUTE_HALF(As1, Ws1, 8);
        if (c2 < 7) {
            CONV_STS(As0, Ws0);
            __syncthreads();
        }
    }

    // ---- epilogue: bias + relu + per-row score (h . p / ||p||) ----
    float pv[4];
    float pn = 0.f;
#pragma unroll
    for (int j = 0; j < 4; ++j) {
        pv[j] = __ldg(&p[cx + 32 * j]);
        pn += pv[j] * pv[j];
    }
#pragma unroll
    for (int o = 16; o; o >>= 1) pn += __shfl_xor_sync(0xffffffffu, pn, o);
    float pinv = rsqrtf(pn);

#pragma unroll
    for (int r = 0; r < 8; ++r) {
        float slo = 0.f, shi = 0.f;
        int row = row0 + ry * 16 + 2 * r;
#pragma unroll
        for (int j = 0; j < 4; ++j) {
            int col = cx + 32 * j;
            float bb = __ldg(&bias[col]);
            float lo, hi;
            unpk2(acc[r][j], lo, hi);
            lo = fmaxf(lo + bb, 0.f);
            hi = fmaxf(hi + bb, 0.f);
            Out[(size_t)row * 128 + col]       = lo;
            Out[(size_t)(row + 1) * 128 + col] = hi;
            slo += lo * pv[j];
            shi += hi * pv[j];
        }
#pragma unroll
        for (int o = 16; o; o >>= 1) {
            slo += __shfl_xor_sync(0xffffffffu, slo, o);
            shi += __shfl_xor_sync(0xffffffffu, shi, o);
        }
        if (cx == 0) {
            g_score[row]     = slo * pinv;
            g_score[row + 1] = shi * pinv;
        }
    }
}

// ---------------- pool: topk + gate + readout (one block per graph) ----------------
template<int LAYER>
__global__ void __launch_bounds__(512)
pool_kernel() {
    constexpr int KK = (LAYER == 1) ? KEEP1 : KEEP2;
    float* h = (LAYER == 1) ? g_h : g_h2;
    float* xout = (LAYER == 1) ? g_x1 : g_x2;

    int b = blockIdx.x;
    int tid = threadIdx.x;
    int lane = tid & 31, w = tid >> 5;   // 16 warps

    __shared__ float sval[512];
    __shared__ float ssort[512];
    __shared__ float sgate[512];
    __shared__ int   ssel[512];
    __shared__ int   sscan[512];
    __shared__ float rmax[16 * 128];
    __shared__ float rsum[16 * 128];

    float* hb = h + (size_t)b * NNODE * 128;

    // scores: precomputed by GEMM epilogue
    {
        float s = g_score[b * NNODE + tid];
        if (LAYER == 2 && !g_m1[b * NNODE + tid]) s = -INFINITY;
        sval[tid] = s;
        ssort[tid] = s;
    }
    __syncthreads();

    // bitonic sort (descending) to find threshold = K-th largest
    for (int k2 = 2; k2 <= 512; k2 <<= 1) {
        for (int j = k2 >> 1; j > 0; j >>= 1) {
            int ixj = tid ^ j;
            float a = ssort[tid];
            float bv = ssort[ixj];
            bool desc = ((tid & k2) == 0);
            bool isLower = (tid < ixj);
            float res = (desc == isLower) ? fmaxf(a, bv) : fminf(a, bv);
            __syncthreads();
            ssort[tid] = res;
            __syncthreads();
        }
    }
    float t = ssort[KK - 1];

    // exact selection with lowest-index tie-break (matches lax.top_k)
    float s = sval[tid];
    int fgt = (s > t) ? 1 : 0;
    int feq = (s == t) ? 1 : 0;
    sscan[tid] = (fgt << 16) | feq;
    __syncthreads();
    for (int off = 1; off < 512; off <<= 1) {
        int v = (tid >= off) ? sscan[tid - off] : 0;
        __syncthreads();
        sscan[tid] += v;
        __syncthreads();
    }
    int totgt = sscan[511] >> 16;
    int preeq = (sscan[tid] & 0xffff) - feq;
    int sel = fgt | (feq && (preeq < KK - totgt));
    ssel[tid] = sel;
    sgate[tid] = sel ? tanhf(s) : 0.f;
    if (LAYER == 1) g_m1[b * NNODE + tid] = (unsigned char)sel;
    __syncthreads();

    // gate (+writeback for layer1) + readout (max & mean over kept nodes)
    float mx0 = -INFINITY, mx1 = -INFINITY, mx2 = -INFINITY, mx3 = -INFINITY;
    float sm0 = 0.f, sm1 = 0.f, sm2 = 0.f, sm3 = 0.f;
    for (int n = w; n < NNODE; n += 16) {
        float g = sgate[n];
        int se = ssel[n];
        float* r = hb + n * 128;
        float v0 = r[lane] * g;
        float v1 = r[lane + 32] * g;
        float v2 = r[lane + 64] * g;
        float v3 = r[lane + 96] * g;
        if (LAYER == 1) {
            r[lane] = v0; r[lane + 32] = v1; r[lane + 64] = v2; r[lane + 96] = v3;
        }
        if (se) {
            mx0 = fmaxf(mx0, v0); mx1 = fmaxf(mx1, v1);
            mx2 = fmaxf(mx2, v2); mx3 = fmaxf(mx3, v3);
        }
        sm0 += v0; sm1 += v1; sm2 += v2; sm3 += v3;
    }
    rmax[w * 128 + lane]      = mx0;
    rmax[w * 128 + lane + 32] = mx1;
    rmax[w * 128 + lane + 64] = mx2;
    rmax[w * 128 + lane + 96] = mx3;
    rsum[w * 128 + lane]      = sm0;
    rsum[w * 128 + lane + 32] = sm1;
    rsum[w * 128 + lane + 64] = sm2;
    rsum[w * 128 + lane + 96] = sm3;
    __syncthreads();
    if (tid < 128) {
        float M = -INFINITY, S = 0.f;
#pragma unroll
        for (int i = 0; i < 16; ++i) {
            M = fmaxf(M, rmax[i * 128 + tid]);
            S += rsum[i * 128 + tid];
        }
        xout[b * 256 + tid] = M;
        xout[b * 256 + 128 + tid] = S / (float)KK;
    }
}

// ---------------- MLP head ----------------
__global__ void __launch_bounds__(128)
head_kernel(const float* __restrict__ lw1, const float* __restrict__ lb1,
            const float* __restrict__ lw2, const float* __restrict__ lb2,
            const float* __restrict__ lw3, const float* __restrict__ lb3,
            float* __restrict__ out) {
    int b = blockIdx.x;
    int tid = threadIdx.x;   // 128
    __shared__ float z[256], z1[128], z2[64];
    z[tid]       = g_x1[b * 256 + tid]       + g_x2[b * 256 + tid];
    z[tid + 128] = g_x1[b * 256 + 128 + tid] + g_x2[b * 256 + 128 + tid];
    __syncthreads();
    float a = lb1[tid];
#pragma unroll 8
    for (int i = 0; i < 256; ++i) a += z[i] * lw1[i * 128 + tid];
    z1[tid] = fmaxf(a, 0.f);
    __syncthreads();
    if (tid < 64) {
        float a2 = lb2[tid];
#pragma unroll 8
        for (int i = 0; i < 128; ++i) a2 += z1[i] * lw2[i * 64 + tid];
        z2[tid] = fmaxf(a2, 0.f);
    }
    __syncthreads();
    if (tid == 0) {
        float a3 = lb3[0];
#pragma unroll 8
        for (int i = 0; i < 64; ++i) a3 += z2[i] * lw3[i];
        out[b] = 1.f / (1.f + expf(-a3));
    }
}

// ---------------- launch ----------------
extern "C" void kernel_launch(void* const* d_in, const int* in_sizes, int n_in,
                              void* d_out, int out_size) {
    const float* x   = (const float*)d_in[0];
    const int*   ei  = (const int*)d_in[1];
    const float* W1r = (const float*)d_in[2];
    const float* W1n = (const float*)d_in[3];
    const float* b1  = (const float*)d_in[4];
    const float* p1  = (const float*)d_in[5];
    const float* W2r = (const float*)d_in[6];
    const float* W2n = (const float*)d_in[7];
    const float* b2  = (const float*)d_in[8];
    const float* p2  = (const float*)d_in[9];
    const float* lw1 = (const float*)d_in[10];
    const float* lb1 = (const float*)d_in[11];
    const float* lw2 = (const float*)d_in[12];
    const float* lb2 = (const float*)d_in[13];
    const float* lw3 = (const float*)d_in[14];
    const float* lb3 = (const float*)d_in[15];
    float* out = (float*)d_out;

    const int* src = ei;
    const int* dst = ei + EDGES;

    // edge buckets (edges are an input, rebuilt every call — stateless)
    zero_kernel<<<NN / 256, 256>>>();
    bucket_scatter_kernel<<<EDGES / 256, 256>>>(src, dst);

    // conv1 + pool1
    agg_gather_kernel<1><<<NN * 32 / 256, 256>>>(x);
    conv_gemm_kernel<1><<<NN / 128, 256>>>(x, W1r, W1n, b1, p1);
    pool_kernel<1><<<BGRAPH, 512>>>();

    // conv2 + pool2 (on gated h)
    agg_gather_kernel<2><<<NN * 32 / 256, 256>>>(nullptr);
    conv_gemm_kernel<2><<<NN / 128, 256>>>(nullptr, W2r, W2n, b2, p2);
    pool_kernel<2><<<BGRAPH, 512>>>();

    // head
    head_kernel<<<BGRAPH, 128>>>(lw1, lb1, lw2, lb2, lw3, lb3, out);
}

// round 17
// speedup vs baseline: 1.0552x; 1.0552x over previous
#include <cuda_runtime.h>
#include <cuda_bf16.h>
#include <stdint.h>
#include <math.h>

// Problem constants
#define BGRAPH 128
#define NNODE  512
#define NN     (BGRAPH*NNODE)      // 65536
#define DFEAT  128
#define EDGES  524288
#define KEEP1  410
#define KEEP2  328
#define BUCKET_CAP 32

// ---------------- scratch (device globals; no runtime allocation) ----------------
__device__ float g_agg[NN*DFEAT];   // aggregated neighbor features
__device__ float g_h  [NN*DFEAT];   // conv1 output (gated in place by pool1)
__device__ float g_h2 [NN*DFEAT];   // conv2 output
__device__ float g_score[NN];       // node scores (written by GEMM epilogue)
__device__ float g_WT[4*128*128];   // transposed weights: [W1r^T, W1n^T, W2r^T, W2n^T]
__device__ int   g_deg[NN];
__device__ int   g_bucket[NN*BUCKET_CAP];
__device__ int   g_ovf_cnt;
__device__ int   g_ovf_d[EDGES];
__device__ int   g_ovf_s[EDGES];
__device__ unsigned char g_m1[NN];
__device__ float g_x1[BGRAPH*256];
__device__ float g_x2[BGRAPH*256];

// ---------------- mma.sync tf32 helpers (standard PTX, compute_103-safe) ----------
__device__ __forceinline__ void mma_tf32(float* d,
                                         unsigned int a0, unsigned int a1,
                                         unsigned int a2, unsigned int a3,
                                         unsigned int b0, unsigned int b1) {
    asm volatile(
        "mma.sync.aligned.m16n8k8.row.col.f32.tf32.tf32.f32 "
        "{%0,%1,%2,%3}, {%4,%5,%6,%7}, {%8,%9}, {%0,%1,%2,%3};\n"
        : "+f"(d[0]), "+f"(d[1]), "+f"(d[2]), "+f"(d[3])
        : "r"(a0), "r"(a1), "r"(a2), "r"(a3), "r"(b0), "r"(b1));
}

// split fp32 into tf32-exact hi (10 mantissa bits) + exact residual lo
__device__ __forceinline__ void split_tf32(float v, unsigned int& hi, unsigned int& lo) {
    unsigned int h = __float_as_uint(v) & 0xFFFFE000u;
    hi = h;
    lo = __float_as_uint(v - __uint_as_float(h));
}

// ---------------- bucketed edge build ----------------
__global__ void zero_kernel() {
    int i = blockIdx.x * blockDim.x + threadIdx.x;
    if (i < NN) g_deg[i] = 0;
    if (i == 0) g_ovf_cnt = 0;
}

__global__ void bucket_scatter_kernel(const int* __restrict__ src,
                                      const int* __restrict__ dst) {
    int i = blockIdx.x * blockDim.x + threadIdx.x;
    if (i < EDGES) {
        int d = dst[i];
        int s = src[i];
        int pos = atomicAdd(&g_deg[d], 1);
        if (pos < BUCKET_CAP) {
            g_bucket[d * BUCKET_CAP + pos] = s;
        } else {
            int o = atomicAdd(&g_ovf_cnt, 1);
            g_ovf_d[o] = d;
            g_ovf_s[o] = s;
        }
    }
}

// ---------------- weight transpose: g_WT[i][n][k] = W_i[k][n] ----------------
__global__ void transpose_w_kernel(const float* __restrict__ W1r, const float* __restrict__ W1n,
                                   const float* __restrict__ W2r, const float* __restrict__ W2n) {
    int i = blockIdx.y;
    const float* W = (i == 0) ? W1r : (i == 1) ? W1n : (i == 2) ? W2r : W2n;
    int idx = blockIdx.x * 256 + threadIdx.x;   // 16384 per matrix
    int n = idx >> 7, k = idx & 127;
    g_WT[i * 16384 + n * 128 + k] = __ldg(&W[k * 128 + n]);
}

// ---------------- neighbor aggregation: warp/node, bucket idx, MLP=8 ----------------
template<int LAYER>
__global__ void __launch_bounds__(256)
agg_gather_kernel(const float* __restrict__ xin) {
    const float* feat = (LAYER == 1) ? xin : g_h;
    int gw = (blockIdx.x * blockDim.x + threadIdx.x) >> 5;
    int lane = threadIdx.x & 31;
    if (gw >= NN) return;

    int nv = __ldg(&g_deg[gw]);
    int m = min(nv, BUCKET_CAP);
    int idx = 0;
    if (lane < m) idx = __ldg(&g_bucket[gw * BUCKET_CAP + lane]);

    const float4* f4 = (const float4*)feat;
    float a0 = 0.f, a1 = 0.f, a2 = 0.f, a3 = 0.f;
    int e = 0;
    for (; e + 8 <= m; e += 8) {
        int i0 = __shfl_sync(0xffffffffu, idx, e);
        int i1 = __shfl_sync(0xffffffffu, idx, e + 1);
        int i2 = __shfl_sync(0xffffffffu, idx, e + 2);
        int i3 = __shfl_sync(0xffffffffu, idx, e + 3);
        int i4 = __shfl_sync(0xffffffffu, idx, e + 4);
        int i5 = __shfl_sync(0xffffffffu, idx, e + 5);
        int i6 = __shfl_sync(0xffffffffu, idx, e + 6);
        int i7 = __shfl_sync(0xffffffffu, idx, e + 7);
        float4 v0 = __ldg(f4 + (size_t)i0 * 32 + lane);
        float4 v1 = __ldg(f4 + (size_t)i1 * 32 + lane);
        float4 v2 = __ldg(f4 + (size_t)i2 * 32 + lane);
        float4 v3 = __ldg(f4 + (size_t)i3 * 32 + lane);
        float4 v4 = __ldg(f4 + (size_t)i4 * 32 + lane);
        float4 v5 = __ldg(f4 + (size_t)i5 * 32 + lane);
        float4 v6 = __ldg(f4 + (size_t)i6 * 32 + lane);
        float4 v7 = __ldg(f4 + (size_t)i7 * 32 + lane);
        a0 += ((v0.x + v1.x) + (v2.x + v3.x)) + ((v4.x + v5.x) + (v6.x + v7.x));
        a1 += ((v0.y + v1.y) + (v2.y + v3.y)) + ((v4.y + v5.y) + (v6.y + v7.y));
        a2 += ((v0.z + v1.z) + (v2.z + v3.z)) + ((v4.z + v5.z) + (v6.z + v7.z));
        a3 += ((v0.w + v1.w) + (v2.w + v3.w)) + ((v4.w + v5.w) + (v6.w + v7.w));
    }
    for (; e + 4 <= m; e += 4) {
        int i0 = __shfl_sync(0xffffffffu, idx, e);
        int i1 = __shfl_sync(0xffffffffu, idx, e + 1);
        int i2 = __shfl_sync(0xffffffffu, idx, e + 2);
        int i3 = __shfl_sync(0xffffffffu, idx, e + 3);
        float4 v0 = __ldg(f4 + (size_t)i0 * 32 + lane);
        float4 v1 = __ldg(f4 + (size_t)i1 * 32 + lane);
        float4 v2 = __ldg(f4 + (size_t)i2 * 32 + lane);
        float4 v3 = __ldg(f4 + (size_t)i3 * 32 + lane);
        a0 += (v0.x + v1.x) + (v2.x + v3.x);
        a1 += (v0.y + v1.y) + (v2.y + v3.y);
        a2 += (v0.z + v1.z) + (v2.z + v3.z);
        a3 += (v0.w + v1.w) + (v2.w + v3.w);
    }
    for (; e < m; ++e) {
        int i0 = __shfl_sync(0xffffffffu, idx, e);
        float4 v0 = __ldg(f4 + (size_t)i0 * 32 + lane);
        a0 += v0.x; a1 += v0.y; a2 += v0.z; a3 += v0.w;
    }
    if (nv > BUCKET_CAP) {   // correctness fallback; ~never taken
        int oc = g_ovf_cnt;
        for (int t = 0; t < oc; ++t) {
            if (g_ovf_d[t] == gw) {
                float4 v0 = __ldg(f4 + (size_t)g_ovf_s[t] * 32 + lane);
                a0 += v0.x; a1 += v0.y; a2 += v0.z; a3 += v0.w;
            }
        }
    }
    ((float4*)g_agg)[(size_t)gw * 32 + lane] = make_float4(a0, a1, a2, a3);
}

// ---------------- conv GEMM via mma.sync tf32 (3-term compensated) ----------------
// Tile 128x128, K=256 (8 chunks of 32: chunks 0-3 A1 x Wr, 4-7 agg x Wn).
// 8 warps: warp w owns rows [16w,16w+16), all 128 cols = 16 m16n8 tiles.
// Full fp32-grade accuracy: D = Ah@Bh + Al@Bh + Ah@Bl (err ~2^-21).
// smem stride 36 -> conflict-free fragment loads (addr mod 32 = 4g+c distinct).

template<int LAYER>
__global__ void __launch_bounds__(256)
conv_mma_kernel(const float* __restrict__ A1in,
                const float* __restrict__ bias,
                const float* __restrict__ p) {
    __shared__ float A_s[128][36];
    __shared__ float W_s[128][36];
    __shared__ float sbias[128];
    __shared__ float sp[128];

    const float* A1 = (LAYER == 1) ? A1in : g_h;
    float* Out = (LAYER == 1) ? g_h : g_h2;

    int tid = threadIdx.x;
    int wid = tid >> 5, lane = tid & 31;
    int row0 = blockIdx.x * 128;
    int g = lane >> 2;         // quad group 0..7
    int q = lane & 3;          // 0..3

    if (tid < 128) { sbias[tid] = __ldg(&bias[tid]); sp[tid] = __ldg(&p[tid]); }

    float acc[16][4];
#pragma unroll
    for (int t = 0; t < 16; ++t)
#pragma unroll
        for (int j = 0; j < 4; ++j) acc[t][j] = 0.f;

#pragma unroll 1
    for (int c = 0; c < 8; ++c) {
        const float* A = (c < 4) ? A1 : g_agg;
        const float* W = g_WT + ((LAYER - 1) * 2 + (c >= 4 ? 1 : 0)) * 16384;
        int k0 = (c & 3) * 32;

        __syncthreads();   // previous chunk's fragment reads done
#pragma unroll
        for (int i = 0; i < 4; ++i) {
            int idx = tid + i * 256;        // 0..1023 float4 slots
            int row = idx >> 3, qq = idx & 7;
            float4 va = *(const float4*)&A[(size_t)(row0 + row) * 128 + k0 + 4 * qq];
            float4 vw = *(const float4*)&W[(size_t)row * 128 + k0 + 4 * qq];
            *(float4*)&A_s[row][4 * qq] = va;
            *(float4*)&W_s[row][4 * qq] = vw;
        }
        __syncthreads();

#pragma unroll
        for (int ks = 0; ks < 4; ++ks) {
            int kk = ks * 8;
            // A fragment for this k8-step
            int ar = wid * 16 + g;
            float fa0 = A_s[ar][kk + q];
            float fa1 = A_s[ar + 8][kk + q];
            float fa2 = A_s[ar][kk + q + 4];
            float fa3 = A_s[ar + 8][kk + q + 4];
            unsigned int ah0, al0, ah1, al1, ah2, al2, ah3, al3;
            split_tf32(fa0, ah0, al0);
            split_tf32(fa1, ah1, al1);
            split_tf32(fa2, ah2, al2);
            split_tf32(fa3, ah3, al3);

#pragma unroll
            for (int t = 0; t < 16; ++t) {
                int br = t * 8 + g;
                float fb0 = W_s[br][kk + q];
                float fb1 = W_s[br][kk + q + 4];
                unsigned int bh0, bl0, bh1, bl1;
                split_tf32(fb0, bh0, bl0);
                split_tf32(fb1, bh1, bl1);
                mma_tf32(acc[t], ah0, ah1, ah2, ah3, bh0, bh1);
                mma_tf32(acc[t], al0, al1, al2, al3, bh0, bh1);
                mma_tf32(acc[t], ah0, ah1, ah2, ah3, bl0, bl1);
            }
        }
    }

    // ---- epilogue: bias + relu + score + store ----
    // pinv (warp-level)
    float pv = sp[lane] * sp[lane] + sp[lane + 32] * sp[lane + 32]
             + sp[lane + 64] * sp[lane + 64] + sp[lane + 96] * sp[lane + 96];
#pragma unroll
    for (int o = 16; o; o >>= 1) pv += __shfl_xor_sync(0xffffffffu, pv, o);
    float pinv = rsqrtf(pv);

    int r0 = row0 + wid * 16 + g;
    int r1 = r0 + 8;
    float sc0 = 0.f, sc1 = 0.f;
#pragma unroll
    for (int t = 0; t < 16; ++t) {
        int c0 = t * 8 + 2 * q;
        float b0 = sbias[c0], b1 = sbias[c0 + 1];
        float p0 = sp[c0], p1v = sp[c0 + 1];
        float v00 = fmaxf(acc[t][0] + b0, 0.f);
        float v01 = fmaxf(acc[t][1] + b1, 0.f);
        float v10 = fmaxf(acc[t][2] + b0, 0.f);
        float v11 = fmaxf(acc[t][3] + b1, 0.f);
        *(float2*)&Out[(size_t)r0 * 128 + c0] = make_float2(v00, v01);
        *(float2*)&Out[(size_t)r1 * 128 + c0] = make_float2(v10, v11);
        sc0 += v00 * p0 + v01 * p1v;
        sc1 += v10 * p0 + v11 * p1v;
    }
    // quad reduce (lanes 4g..4g+3)
    sc0 += __shfl_xor_sync(0xffffffffu, sc0, 1);
    sc0 += __shfl_xor_sync(0xffffffffu, sc0, 2);
    sc1 += __shfl_xor_sync(0xffffffffu, sc1, 1);
    sc1 += __shfl_xor_sync(0xffffffffu, sc1, 2);
    if (q == 0) {
        g_score[r0] = sc0 * pinv;
        g_score[r1] = sc1 * pinv;
    }
}

// ---------------- pool: topk + gate + readout (one block per graph) ----------------
template<int LAYER>
__global__ void __launch_bounds__(512)
pool_kernel() {
    constexpr int KK = (LAYER == 1) ? KEEP1 : KEEP2;
    float* h = (LAYER == 1) ? g_h : g_h2;
    float* xout = (LAYER == 1) ? g_x1 : g_x2;

    int b = blockIdx.x;
    int tid = threadIdx.x;
    int lane = tid & 31, w = tid >> 5;   // 16 warps

    __shared__ float sval[512];
    __shared__ float ssort[512];
    __shared__ float sgate[512];
    __shared__ int   ssel[512];
    __shared__ int   sscan[512];
    __shared__ float rmax[16 * 128];
    __shared__ float rsum[16 * 128];

    float* hb = h + (size_t)b * NNODE * 128;

    // scores: precomputed by GEMM epilogue
    {
        float s = g_score[b * NNODE + tid];
        if (LAYER == 2 && !g_m1[b * NNODE + tid]) s = -INFINITY;
        sval[tid] = s;
        ssort[tid] = s;
    }
    __syncthreads();

    // bitonic sort (descending) to find threshold = K-th largest
    for (int k2 = 2; k2 <= 512; k2 <<= 1) {
        for (int j = k2 >> 1; j > 0; j >>= 1) {
            int ixj = tid ^ j;
            float a = ssort[tid];
            float bv = ssort[ixj];
            bool desc = ((tid & k2) == 0);
            bool isLower = (tid < ixj);
            float res = (desc == isLower) ? fmaxf(a, bv) : fminf(a, bv);
            __syncthreads();
            ssort[tid] = res;
            __syncthreads();
        }
    }
    float t = ssort[KK - 1];

    // exact selection with lowest-index tie-break (matches lax.top_k)
    float s = sval[tid];
    int fgt = (s > t) ? 1 : 0;
    int feq = (s == t) ? 1 : 0;
    sscan[tid] = (fgt << 16) | feq;
    __syncthreads();
    for (int off = 1; off < 512; off <<= 1) {
        int v = (tid >= off) ? sscan[tid - off] : 0;
        __syncthreads();
        sscan[tid] += v;
        __syncthreads();
    }
    int totgt = sscan[511] >> 16;
    int preeq = (sscan[tid] & 0xffff) - feq;
    int sel = fgt | (feq && (preeq < KK - totgt));
    ssel[tid] = sel;
    sgate[tid] = sel ? tanhf(s) : 0.f;
    if (LAYER == 1) g_m1[b * NNODE + tid] = (unsigned char)sel;
    __syncthreads();

    // gate (+writeback for layer1) + readout (max & mean over kept nodes)
    float mx0 = -INFINITY, mx1 = -INFINITY, mx2 = -INFINITY, mx3 = -INFINITY;
    float sm0 = 0.f, sm1 = 0.f, sm2 = 0.f, sm3 = 0.f;
    for (int n = w; n < NNODE; n += 16) {
        float g = sgate[n];
        int se = ssel[n];
        float* r = hb + n * 128;
        float v0 = r[lane] * g;
        float v1 = r[lane + 32] * g;
        float v2 = r[lane + 64] * g;
        float v3 = r[lane + 96] * g;
        if (LAYER == 1) {
            r[lane] = v0; r[lane + 32] = v1; r[lane + 64] = v2; r[lane + 96] = v3;
        }
        if (se) {
            mx0 = fmaxf(mx0, v0); mx1 = fmaxf(mx1, v1);
            mx2 = fmaxf(mx2, v2); mx3 = fmaxf(mx3, v3);
        }
        sm0 += v0; sm1 += v1; sm2 += v2; sm3 += v3;
    }
    rmax[w * 128 + lane]      = mx0;
    rmax[w * 128 + lane + 32] = mx1;
    rmax[w * 128 + lane + 64] = mx2;
    rmax[w * 128 + lane + 96] = mx3;
    rsum[w * 128 + lane]      = sm0;
    rsum[w * 128 + lane + 32] = sm1;
    rsum[w * 128 + lane + 64] = sm2;
    rsum[w * 128 + lane + 96] = sm3;
    __syncthreads();
    if (tid < 128) {
        float M = -INFINITY, S = 0.f;
#pragma unroll
        for (int i = 0; i < 16; ++i) {
            M = fmaxf(M, rmax[i * 128 + tid]);
            S += rsum[i * 128 + tid];
        }
        xout[b * 256 + tid] = M;
        xout[b * 256 + 128 + tid] = S / (float)KK;
    }
}

// ---------------- MLP head ----------------
__global__ void __launch_bounds__(128)
head_kernel(const float* __restrict__ lw1, const float* __restrict__ lb1,
            const float* __restrict__ lw2, const float* __restrict__ lb2,
            const float* __restrict__ lw3, const float* __restrict__ lb3,
            float* __restrict__ out) {
    int b = blockIdx.x;
    int tid = threadIdx.x;   // 128
    __shared__ float z[256], z1[128], z2[64];
    z[tid]       = g_x1[b * 256 + tid]       + g_x2[b * 256 + tid];
    z[tid + 128] = g_x1[b * 256 + 128 + tid] + g_x2[b * 256 + 128 + tid];
    __syncthreads();
    float a = lb1[tid];
#pragma unroll 8
    for (int i = 0; i < 256; ++i) a += z[i] * lw1[i * 128 + tid];
    z1[tid] = fmaxf(a, 0.f);
    __syncthreads();
    if (tid < 64) {
        float a2 = lb2[tid];
#pragma unroll 8
        for (int i = 0; i < 128; ++i) a2 += z1[i] * lw2[i * 64 + tid];
        z2[tid] = fmaxf(a2, 0.f);
    }
    __syncthreads();
    if (tid == 0) {
        float a3 = lb3[0];
#pragma unroll 8
        for (int i = 0; i < 64; ++i) a3 += z2[i] * lw3[i];
        out[b] = 1.f / (1.f + expf(-a3));
    }
}

// ---------------- launch ----------------
extern "C" void kernel_launch(void* const* d_in, const int* in_sizes, int n_in,
                              void* d_out, int out_size) {
    const float* x   = (const float*)d_in[0];
    const int*   ei  = (const int*)d_in[1];
    const float* W1r = (const float*)d_in[2];
    const float* W1n = (const float*)d_in[3];
    const float* b1  = (const float*)d_in[4];
    const float* p1  = (const float*)d_in[5];
    const float* W2r = (const float*)d_in[6];
    const float* W2n = (const float*)d_in[7];
    const float* b2  = (const float*)d_in[8];
    const float* p2  = (const float*)d_in[9];
    const float* lw1 = (const float*)d_in[10];
    const float* lb1 = (const float*)d_in[11];
    const float* lw2 = (const float*)d_in[12];
    const float* lb2 = (const float*)d_in[13];
    const float* lw3 = (const float*)d_in[14];
    const float* lb3 = (const float*)d_in[15];
    float* out = (float*)d_out;

    const int* src = ei;
    const int* dst = ei + EDGES;

    // edge buckets + weight transposes
    zero_kernel<<<NN / 256, 256>>>();
    bucket_scatter_kernel<<<EDGES / 256, 256>>>(src, dst);
    transpose_w_kernel<<<dim3(64, 4), 256>>>(W1r, W1n, W2r, W2n);

    // conv1 + pool1
    agg_gather_kernel<1><<<NN * 32 / 256, 256>>>(x);
    conv_mma_kernel<1><<<NN / 128, 256>>>(x, b1, p1);
    pool_kernel<1><<<BGRAPH, 512>>>();

    // conv2 + pool2 (on gated h)
    agg_gather_kernel<2><<<NN * 32 / 256, 256>>>(nullptr);
    conv_mma_kernel<2><<<NN / 128, 256>>>(nullptr, b2, p2);
    pool_kernel<2><<<BGRAPH, 512>>>();

    // head
    head_kernel<<<BGRAPH, 128>>>(lw1, lb1, lw2, lb2, lw3, lb3, out);
}